// round 13
// baseline (speedup 1.0000x reference)
#include <cuda_runtime.h>
#include <cuda_bf16.h>

#define B_   8
#define N_   1024
#define D_   768
#define H_   12
#define HD_  64
#define ROWS (B_ * N_)      // 8192
#define D3_  (3 * D_)       // 2304
#define SCALE_ 0.125f
#define NBH  (B_ * H_)      // 96

// ---------------- split bf16 scratch (alloc-free rule: device globals) -----
__device__ __align__(16) unsigned short g_Xh[ROWS * D_];
__device__ __align__(16) unsigned short g_Xl[ROWS * D_];
__device__ __align__(16) unsigned short g_Wqh[D_ * D3_];
__device__ __align__(16) unsigned short g_Wql[D_ * D3_];
__device__ __align__(16) unsigned short g_Wmh[D_ * D_];
__device__ __align__(16) unsigned short g_Wml[D_ * D_];
__device__ __align__(16) unsigned short g_Qh[NBH * N_ * HD_];
__device__ __align__(16) unsigned short g_Ql[NBH * N_ * HD_];
__device__ __align__(16) unsigned short g_Kh[NBH * N_ * HD_];
__device__ __align__(16) unsigned short g_Kl[NBH * N_ * HD_];
__device__ __align__(16) unsigned short g_Vth[NBH * HD_ * N_];  // [bh][hd][key]
__device__ __align__(16) unsigned short g_Vtl[NBH * HD_ * N_];
__device__ __align__(16) unsigned short g_Ah[ROWS * D_];        // attn out hi
__device__ __align__(16) unsigned short g_Al[ROWS * D_];        // attn out lo

// ---------------- helpers --------------------------------------------------
// paired split via cvt.rn.bf16x2 (RNE):
// H = bf16(v0) | bf16(v1)<<16 ; L = bf16(v0-hi0) | bf16(v1-hi1)<<16
__device__ __forceinline__ void split2(float v0, float v1, unsigned& H, unsigned& L) {
  asm("cvt.rn.bf16x2.f32 %0, %1, %2;" : "=r"(H) : "f"(v1), "f"(v0));
  float h0 = __uint_as_float(H << 16);
  float h1 = __uint_as_float(H & 0xFFFF0000u);
  float l0 = v0 - h0, l1 = v1 - h1;
  asm("cvt.rn.bf16x2.f32 %0, %1, %2;" : "=r"(L) : "f"(l1), "f"(l0));
}
__device__ __forceinline__ void mma16816(float* c, const unsigned* a,
                                         unsigned b0, unsigned b1) {
  asm volatile(
      "mma.sync.aligned.m16n8k16.row.col.f32.bf16.bf16.f32 "
      "{%0,%1,%2,%3}, {%4,%5,%6,%7}, {%8,%9}, {%0,%1,%2,%3};\n"
      : "+f"(c[0]), "+f"(c[1]), "+f"(c[2]), "+f"(c[3])
      : "r"(a[0]), "r"(a[1]), "r"(a[2]), "r"(a[3]), "r"(b0), "r"(b1));
}
__device__ __forceinline__ void ldsm4(unsigned* r, unsigned a) {
  asm volatile("ldmatrix.sync.aligned.m8n8.x4.shared.b16 {%0,%1,%2,%3}, [%4];\n"
               : "=r"(r[0]), "=r"(r[1]), "=r"(r[2]), "=r"(r[3]) : "r"(a));
}
__device__ __forceinline__ void ldsm4t(unsigned* r, unsigned a) {
  asm volatile("ldmatrix.sync.aligned.m8n8.x4.trans.shared.b16 {%0,%1,%2,%3}, [%4];\n"
               : "=r"(r[0]), "=r"(r[1]), "=r"(r[2]), "=r"(r[3]) : "r"(a));
}
__device__ __forceinline__ void cp16(void* smem, const void* gmem) {
  unsigned s = (unsigned)__cvta_generic_to_shared(smem);
  asm volatile("cp.async.cg.shared.global [%0], [%1], 16;\n" :: "r"(s), "l"(gmem));
}
#define CP_COMMIT() asm volatile("cp.async.commit_group;\n" ::: "memory")
#define CP_WAIT(n)  asm volatile("cp.async.wait_group %0;\n" :: "n"(n) : "memory")

// ---------------- pre-split: fp32 -> hi/lo bf16 ----------------------------
__global__ void split4(const float4* __restrict__ src, uint2* __restrict__ dh,
                       uint2* __restrict__ dl, int n4) {
  int i = blockIdx.x * blockDim.x + threadIdx.x;
  if (i >= n4) return;
  float4 v = src[i];
  unsigned H0, L0, H1, L1;
  split2(v.x, v.y, H0, L0);
  split2(v.z, v.w, H1, L1);
  dh[i] = make_uint2(H0, H1);
  dl[i] = make_uint2(L0, L1);
}

// ---------------------------------------------------------------------------
// Split-bf16 GEMM, CTA 128x256, warp tile 64x64, 1 CTA/SM, 2 warps/SMSP.
// cp.async double-buffer + ldmatrix; term-major mma (acc reuse distance 32).
// SMEM bytes: Ah[2][128][40] @0 | Al @20480 | Bh[2][32][264] @40960 | Bl @74752
// total 108,544 B.
// ---------------------------------------------------------------------------
#define GEMM_SMEM 108544

template <int LDB, int MODE>
__global__ __launch_bounds__(256) void gemm_mma(
    const unsigned short* __restrict__ Agh, const unsigned short* __restrict__ Agl,
    const unsigned short* __restrict__ Bgh, const unsigned short* __restrict__ Bgl,
    const float* __restrict__ aux, float* __restrict__ C)
{
  extern __shared__ __align__(16) unsigned short smem_u16[];
  const int tid = threadIdx.x, lane = tid & 31, warp = tid >> 5;
  const int g = lane >> 2, tg = lane & 3;
  const int wm = (warp >> 2) * 64, wn = (warp & 3) * 64;
  const int bx = blockIdx.x, by = blockIdx.y;

  float acc[4][8][4] = {};

  const unsigned sbase = (unsigned)__cvta_generic_to_shared(smem_u16);
  const unsigned aoff = ((wm + (lane & 15)) * 40 + (lane >> 4) * 8) * 2;
  const unsigned boff = ((lane & 15) * 264 + wn + (lane >> 4) * 8) * 2;

  auto load_stage = [&](int k0, int st) {
    unsigned short* dAh = smem_u16 + st * 5120;
    unsigned short* dAl = smem_u16 + 10240 + st * 5120;
    unsigned short* dBh = smem_u16 + 20480 + st * 8448;
    unsigned short* dBl = smem_u16 + 37376 + st * 8448;
#pragma unroll
    for (int t = 0; t < 2; t++) {            // A: 128 rows x 32 k
      int c = tid + t * 256;
      int ar = c >> 2, ak = (c & 3) * 8;
      size_t ga = (size_t)(by * 128 + ar) * D_ + k0 + ak;
      cp16(dAh + ar * 40 + ak, Agh + ga);
      cp16(dAl + ar * 40 + ak, Agl + ga);
    }
#pragma unroll
    for (int t = 0; t < 4; t++) {            // B: 32 k x 256 n
      int c = tid + t * 256;
      int br = c >> 5, bn = (c & 31) * 8;
      size_t gb = (size_t)(k0 + br) * LDB + bx * 256 + bn;
      cp16(dBh + br * 264 + bn, Bgh + gb);
      cp16(dBl + br * 264 + bn, Bgl + gb);
    }
    CP_COMMIT();
  };

  load_stage(0, 0);
  for (int it = 0; it < 24; it++) {
    if (it + 1 < 24) {
      load_stage((it + 1) * 32, (it + 1) & 1);
      CP_WAIT(1);
    } else {
      CP_WAIT(0);
    }
    __syncthreads();
    const int st = it & 1;
    const unsigned sAh = sbase + st * 10240;
    const unsigned sAl = sbase + 20480 + st * 10240;
    const unsigned sBh = sbase + 40960 + st * 16896;
    const unsigned sBl = sbase + 74752 + st * 16896;
#pragma unroll
    for (int kk = 0; kk < 2; kk++) {
      unsigned ah[4][4], al[4][4], bh[4][4], bl[4][4];
#pragma unroll
      for (int i = 0; i < 4; i++) {
        ldsm4(ah[i], sAh + aoff + i * 1280 + kk * 32);
        ldsm4(al[i], sAl + aoff + i * 1280 + kk * 32);
      }
#pragma unroll
      for (int jj = 0; jj < 4; jj++) {
        ldsm4t(bh[jj], sBh + boff + kk * 8448 + jj * 32);
        ldsm4t(bl[jj], sBl + boff + kk * 8448 + jj * 32);
      }
      // term-major: 3 passes over 32 accumulators (reuse distance 32)
#pragma unroll
      for (int i = 0; i < 4; i++)
#pragma unroll
        for (int jj = 0; jj < 4; jj++) {
          mma16816(acc[i][2 * jj],     ah[i], bh[jj][0], bh[jj][1]);
          mma16816(acc[i][2 * jj + 1], ah[i], bh[jj][2], bh[jj][3]);
        }
#pragma unroll
      for (int i = 0; i < 4; i++)
#pragma unroll
        for (int jj = 0; jj < 4; jj++) {
          mma16816(acc[i][2 * jj],     ah[i], bl[jj][0], bl[jj][1]);
          mma16816(acc[i][2 * jj + 1], ah[i], bl[jj][2], bl[jj][3]);
        }
#pragma unroll
      for (int i = 0; i < 4; i++)
#pragma unroll
        for (int jj = 0; jj < 4; jj++) {
          mma16816(acc[i][2 * jj],     al[i], bh[jj][0], bh[jj][1]);
          mma16816(acc[i][2 * jj + 1], al[i], bh[jj][2], bh[jj][3]);
        }
    }
    __syncthreads();
  }

  if constexpr (MODE == 0) {
    const int which = bx / 3;   // 0=Q 1=K 2=V  (768 = 3 tiles of 256)
#pragma unroll
    for (int i = 0; i < 4; i++) {
#pragma unroll
      for (int half = 0; half < 2; half++) {
        const int m = by * 128 + wm + i * 16 + g + half * 8;
        const float gate = aux[m];
        const int b = m >> 10, tok = m & 1023;
#pragma unroll
        for (int j = 0; j < 8; j++) {
          const int col = bx * 256 + wn + j * 8 + 2 * tg;
          const int dd = col - which * D_;
          const int h = dd >> 6, hd = dd & 63;
          const int bh = b * H_ + h;
          float v0 = acc[i][j][half * 2 + 0] * gate;
          float v1 = acc[i][j][half * 2 + 1] * gate;
          if (which == 0) { v0 *= SCALE_; v1 *= SCALE_; }
          unsigned Hv, Lv;
          split2(v0, v1, Hv, Lv);
          if (which == 0) {
            const size_t idx = ((size_t)bh * N_ + tok) * HD_ + hd;
            *reinterpret_cast<unsigned*>(&g_Qh[idx]) = Hv;
            *reinterpret_cast<unsigned*>(&g_Ql[idx]) = Lv;
          } else if (which == 1) {
            const size_t idx = ((size_t)bh * N_ + tok) * HD_ + hd;
            *reinterpret_cast<unsigned*>(&g_Kh[idx]) = Hv;
            *reinterpret_cast<unsigned*>(&g_Kl[idx]) = Lv;
          } else {
            const size_t r0 = ((size_t)bh * HD_ + hd) * N_ + tok;
            g_Vth[r0] = (unsigned short)Hv; g_Vth[r0 + N_] = (unsigned short)(Hv >> 16);
            g_Vtl[r0] = (unsigned short)Lv; g_Vtl[r0 + N_] = (unsigned short)(Lv >> 16);
          }
        }
      }
    }
  } else {
#pragma unroll
    for (int i = 0; i < 4; i++)
#pragma unroll
      for (int half = 0; half < 2; half++) {
        const int m = by * 128 + wm + i * 16 + g + half * 8;
#pragma unroll
        for (int j = 0; j < 8; j++) {
          const int col = bx * 256 + wn + j * 8 + 2 * tg;
          float2 o;
          o.x = acc[i][j][half * 2 + 0] + aux[col];
          o.y = acc[i][j][half * 2 + 1] + aux[col + 1];
          *reinterpret_cast<float2*>(&C[(size_t)m * D_ + col]) = o;
        }
      }
  }
}

// ---------------------------------------------------------------------------
// Flash attention (byte-identical to R12 best): 128 queries/CTA, online
// softmax, S/P in registers, K->buf0 / V^T->buf1 cp.async ping-pong,
// interleaved mma, softmax emits fragment-ready bf16x2 hi/lo words.
// ---------------------------------------------------------------------------
#define FA_STG  36864
#define FA_LO   18432
#define FA_SMEM (2 * FA_STG)

__global__ __launch_bounds__(256, 1) void attn_flash()
{
  extern __shared__ __align__(16) unsigned short KV[];
  const unsigned kvb = (unsigned)__cvta_generic_to_shared(KV);

  const int tid = threadIdx.x, lane = tid & 31, warp = tid >> 5;
  const int g = lane >> 2, tg = lane & 3;
  const int bh = blockIdx.y;
  const int q0 = blockIdx.x * 128;
  const size_t kbase = (size_t)bh * N_ * HD_;
  const size_t vbase = (size_t)bh * HD_ * N_;
  const size_t qrow = kbase + (size_t)(q0 + warp * 16 + g) * HD_;

  auto load_k = [&](int kt) {
    unsigned short* dst = KV;
    const unsigned short* sh = g_Kh + kbase + (size_t)kt * 128 * HD_;
    const unsigned short* sl = g_Kl + kbase + (size_t)kt * 128 * HD_;
#pragma unroll
    for (int t = 0; t < 4; t++) {
      int c = tid + t * 256;
      int row = c >> 3, ko = (c & 7) * 8;
      cp16(dst + row * 72 + ko, sh + row * HD_ + ko);
      cp16(dst + 9216 + row * 72 + ko, sl + row * HD_ + ko);
    }
    CP_COMMIT();
  };
  auto load_v = [&](int vt) {
    unsigned short* dst = KV + 18432;
    const unsigned short* sh = g_Vth + vbase + vt * 128;
    const unsigned short* sl = g_Vtl + vbase + vt * 128;
#pragma unroll
    for (int t = 0; t < 4; t++) {
      int c = tid + t * 256;
      int row = c >> 4, no = (c & 15) * 8;
      cp16(dst + row * 136 + no, sh + (size_t)row * N_ + no);
      cp16(dst + 9216 + row * 136 + no, sl + (size_t)row * N_ + no);
    }
    CP_COMMIT();
  };

  load_k(0);
  load_v(0);

  unsigned qh[4][4], ql[4][4];
#pragma unroll
  for (int c = 0; c < 4; c++) {
    const size_t r0 = qrow + c * 16 + 2 * tg;
    const size_t r8 = r0 + 8 * HD_;
    qh[c][0] = *reinterpret_cast<const unsigned*>(&g_Qh[r0]);
    qh[c][1] = *reinterpret_cast<const unsigned*>(&g_Qh[r8]);
    qh[c][2] = *reinterpret_cast<const unsigned*>(&g_Qh[r0 + 8]);
    qh[c][3] = *reinterpret_cast<const unsigned*>(&g_Qh[r8 + 8]);
    ql[c][0] = *reinterpret_cast<const unsigned*>(&g_Ql[r0]);
    ql[c][1] = *reinterpret_cast<const unsigned*>(&g_Ql[r8]);
    ql[c][2] = *reinterpret_cast<const unsigned*>(&g_Ql[r0 + 8]);
    ql[c][3] = *reinterpret_cast<const unsigned*>(&g_Ql[r8 + 8]);
  }

  float oacc[8][4] = {};
  float m0 = -1e30f, m1 = -1e30f, l0 = 0.f, l1 = 0.f;

  const unsigned kfb = ((lane & 15) * 72 + (lane >> 4) * 8) * 2;
  const unsigned vfb = ((lane & 7) * 136 + (lane >> 3) * 8) * 2;

#pragma unroll 1
  for (int kt = 0; kt < 8; kt++) {
    // ---- S = Q K^T ----
    CP_WAIT(1);
    __syncthreads();
    float sacc[16][4] = {};
#pragma unroll
    for (int kg = 0; kg < 8; kg++) {
      const unsigned kb = kvb + kg * 2304 + kfb;
      unsigned kh[4][4], kl[4][4];
#pragma unroll
      for (int c = 0; c < 4; c++) {
        ldsm4(kh[c], kb + c * 32);
        ldsm4(kl[c], kb + FA_LO + c * 32);
      }
      float* s0 = sacc[2 * kg];
      float* s1 = sacc[2 * kg + 1];
#pragma unroll
      for (int c = 0; c < 4; c++) {
        mma16816(s0, qh[c], kh[c][0], kh[c][2]);
        mma16816(s1, qh[c], kh[c][1], kh[c][3]);
      }
#pragma unroll
      for (int c = 0; c < 4; c++) {
        mma16816(s0, qh[c], kl[c][0], kl[c][2]);
        mma16816(s1, qh[c], kl[c][1], kl[c][3]);
      }
#pragma unroll
      for (int c = 0; c < 4; c++) {
        mma16816(s0, ql[c], kh[c][0], kh[c][2]);
        mma16816(s1, ql[c], kh[c][1], kh[c][3]);
      }
    }
    __syncthreads();
    if (kt < 7) load_k(kt + 1);

    // ---- online softmax; emit fragment-ready bf16x2 hi/lo words ----
    float mx0 = -1e30f, mx1 = -1e30f;
#pragma unroll
    for (int t = 0; t < 16; t++) {
      mx0 = fmaxf(mx0, fmaxf(sacc[t][0], sacc[t][1]));
      mx1 = fmaxf(mx1, fmaxf(sacc[t][2], sacc[t][3]));
    }
    mx0 = fmaxf(mx0, __shfl_xor_sync(0xffffffffu, mx0, 1));
    mx0 = fmaxf(mx0, __shfl_xor_sync(0xffffffffu, mx0, 2));
    mx1 = fmaxf(mx1, __shfl_xor_sync(0xffffffffu, mx1, 1));
    mx1 = fmaxf(mx1, __shfl_xor_sync(0xffffffffu, mx1, 2));
    const float m0n = fmaxf(m0, mx0), m1n = fmaxf(m1, mx1);
    const float c0 = __expf(m0 - m0n), c1 = __expf(m1 - m1n);
    m0 = m0n; m1 = m1n;
    float ts0 = 0.f, ts1 = 0.f;
#pragma unroll
    for (int t = 0; t < 16; t++) {
      float p0 = __expf(sacc[t][0] - m0n), p1 = __expf(sacc[t][1] - m0n);
      float p2 = __expf(sacc[t][2] - m1n), p3 = __expf(sacc[t][3] - m1n);
      ts0 += p0 + p1; ts1 += p2 + p3;
      unsigned H01, L01, H23, L23;
      split2(p0, p1, H01, L01);
      split2(p2, p3, H23, L23);
      sacc[t][0] = __uint_as_float(H01);
      sacc[t][1] = __uint_as_float(L01);
      sacc[t][2] = __uint_as_float(H23);
      sacc[t][3] = __uint_as_float(L23);
    }
    ts0 += __shfl_xor_sync(0xffffffffu, ts0, 1);
    ts0 += __shfl_xor_sync(0xffffffffu, ts0, 2);
    ts1 += __shfl_xor_sync(0xffffffffu, ts1, 1);
    ts1 += __shfl_xor_sync(0xffffffffu, ts1, 2);
    l0 = l0 * c0 + ts0;
    l1 = l1 * c1 + ts1;
#pragma unroll
    for (int vn = 0; vn < 8; vn++) {
      oacc[vn][0] *= c0; oacc[vn][1] *= c0;
      oacc[vn][2] *= c1; oacc[vn][3] *= c1;
    }

    // ---- O += P V ----
    CP_WAIT(1);
    if (kt == 7) CP_WAIT(0);
    __syncthreads();
#pragma unroll
    for (int tt = 0; tt < 4; tt++) {
      unsigned pfh[2][4], pfl[2][4];
#pragma unroll
      for (int cc = 0; cc < 2; cc++) {
        const int t0 = (2 * tt + cc) * 2;
        pfh[cc][0] = __float_as_uint(sacc[t0][0]);
        pfh[cc][1] = __float_as_uint(sacc[t0][2]);
        pfh[cc][2] = __float_as_uint(sacc[t0 + 1][0]);
        pfh[cc][3] = __float_as_uint(sacc[t0 + 1][2]);
        pfl[cc][0] = __float_as_uint(sacc[t0][1]);
        pfl[cc][1] = __float_as_uint(sacc[t0][3]);
        pfl[cc][2] = __float_as_uint(sacc[t0 + 1][1]);
        pfl[cc][3] = __float_as_uint(sacc[t0 + 1][3]);
      }
#pragma unroll
      for (int vp = 0; vp < 4; vp++) {
        const int vn0 = 2 * vp, vn1 = 2 * vp + 1;
        const unsigned vb0 = kvb + FA_STG + vn0 * 2176 + vfb + tt * 64;
        const unsigned vb1 = kvb + FA_STG + vn1 * 2176 + vfb + tt * 64;
        unsigned vh0[4], vl0[4], vh1[4], vl1[4];
        ldsm4(vh0, vb0);
        ldsm4(vl0, vb0 + FA_LO);
        ldsm4(vh1, vb1);
        ldsm4(vl1, vb1 + FA_LO);
        float* o0 = oacc[vn0];
        float* o1 = oacc[vn1];
        mma16816(o0, pfh[0], vh0[0], vh0[1]);
        mma16816(o1, pfh[0], vh1[0], vh1[1]);
        mma16816(o0, pfh[0], vl0[0], vl0[1]);
        mma16816(o1, pfh[0], vl1[0], vl1[1]);
        mma16816(o0, pfl[0], vh0[0], vh0[1]);
        mma16816(o1, pfl[0], vh1[0], vh1[1]);
        mma16816(o0, pfh[1], vh0[2], vh0[3]);
        mma16816(o1, pfh[1], vh1[2], vh1[3]);
        mma16816(o0, pfh[1], vl0[2], vl0[3]);
        mma16816(o1, pfh[1], vl1[2], vl1[3]);
        mma16816(o0, pfl[1], vh0[2], vh0[3]);
        mma16816(o1, pfl[1], vh1[2], vh1[3]);
      }
    }
    __syncthreads();
    if (kt < 7) load_v(kt + 1);
  }

  // ---- finalize: normalize, write split bf16 O for GEMM2 ----
  const float inv0 = 1.f / l0, inv1 = 1.f / l1;
  const int b = bh / H_, h = bh - (bh / H_) * H_;
  const int tok = q0 + warp * 16 + g;
  const size_t base0 = (size_t)(b * N_ + tok) * D_ + h * HD_ + 2 * tg;
  const size_t base8 = base0 + (size_t)8 * D_;
#pragma unroll
  for (int vn = 0; vn < 8; vn++) {
    unsigned Hv, Lv;
    split2(oacc[vn][0] * inv0, oacc[vn][1] * inv0, Hv, Lv);
    *reinterpret_cast<unsigned*>(&g_Ah[base0 + vn * 8]) = Hv;
    *reinterpret_cast<unsigned*>(&g_Al[base0 + vn * 8]) = Lv;
    split2(oacc[vn][2] * inv1, oacc[vn][3] * inv1, Hv, Lv);
    *reinterpret_cast<unsigned*>(&g_Ah[base8 + vn * 8]) = Hv;
    *reinterpret_cast<unsigned*>(&g_Al[base8 + vn * 8]) = Lv;
  }
}

// ---------------------------------------------------------------------------
extern "C" void kernel_launch(void* const* d_in, const int* in_sizes, int n_in,
                              void* d_out, int out_size)
{
  const float* x      = (const float*)d_in[0];
  const float* weight = (const float*)d_in[1];
  const float* W_qkv  = (const float*)d_in[2];
  const float* W_msa  = (const float*)d_in[3];
  const float* b_msa  = (const float*)d_in[4];
  float* out = (float*)d_out;

  unsigned short *xh, *xl, *wqh, *wql, *wmh, *wml, *ah, *al;
  cudaGetSymbolAddress((void**)&xh,  g_Xh);  cudaGetSymbolAddress((void**)&xl,  g_Xl);
  cudaGetSymbolAddress((void**)&wqh, g_Wqh); cudaGetSymbolAddress((void**)&wql, g_Wql);
  cudaGetSymbolAddress((void**)&wmh, g_Wmh); cudaGetSymbolAddress((void**)&wml, g_Wml);
  cudaGetSymbolAddress((void**)&ah,  g_Ah);  cudaGetSymbolAddress((void**)&al,  g_Al);

  cudaFuncSetAttribute(gemm_mma<D3_, 0>,
                       cudaFuncAttributeMaxDynamicSharedMemorySize, GEMM_SMEM);
  cudaFuncSetAttribute(gemm_mma<D_, 1>,
                       cudaFuncAttributeMaxDynamicSharedMemorySize, GEMM_SMEM);
  cudaFuncSetAttribute(attn_flash,
                       cudaFuncAttributeMaxDynamicSharedMemorySize, FA_SMEM);

  split4<<<ROWS * D_ / 4 / 256, 256>>>((const float4*)x, (uint2*)xh, (uint2*)xl,
                                       ROWS * D_ / 4);
  split4<<<D_ * D3_ / 4 / 256, 256>>>((const float4*)W_qkv, (uint2*)wqh, (uint2*)wql,
                                      D_ * D3_ / 4);
  split4<<<D_ * D_ / 4 / 256, 256>>>((const float4*)W_msa, (uint2*)wmh, (uint2*)wml,
                                     D_ * D_ / 4);
  gemm_mma<D3_, 0><<<dim3(D3_ / 256, ROWS / 128), 256, GEMM_SMEM>>>(
      xh, xl, wqh, wql, weight, nullptr);
  attn_flash<<<dim3(N_ / 128, NBH), 256, FA_SMEM>>>();
  gemm_mma<D_, 1><<<dim3(D_ / 256, ROWS / 128), 256, GEMM_SMEM>>>(
      ah, al, wmh, wml, b_msa, out);
}

// round 14
// speedup vs baseline: 1.0778x; 1.0778x over previous
#include <cuda_runtime.h>
#include <cuda_bf16.h>

#define B_   8
#define N_   1024
#define D_   768
#define H_   12
#define HD_  64
#define ROWS (B_ * N_)      // 8192
#define D3_  (3 * D_)       // 2304
#define SCALE_ 0.125f
#define NBH  (B_ * H_)      // 96

// ---------------- split bf16 scratch (alloc-free rule: device globals) -----
__device__ __align__(16) unsigned short g_Xh[ROWS * D_];
__device__ __align__(16) unsigned short g_Xl[ROWS * D_];
__device__ __align__(16) unsigned short g_Wqh[D_ * D3_];
__device__ __align__(16) unsigned short g_Wql[D_ * D3_];
__device__ __align__(16) unsigned short g_Wmh[D_ * D_];
__device__ __align__(16) unsigned short g_Wml[D_ * D_];
__device__ __align__(16) unsigned short g_Qh[NBH * N_ * HD_];
__device__ __align__(16) unsigned short g_Ql[NBH * N_ * HD_];
__device__ __align__(16) unsigned short g_Kh[NBH * N_ * HD_];
__device__ __align__(16) unsigned short g_Kl[NBH * N_ * HD_];
__device__ __align__(16) unsigned short g_Vth[NBH * HD_ * N_];  // [bh][hd][key]
__device__ __align__(16) unsigned short g_Vtl[NBH * HD_ * N_];
__device__ __align__(16) unsigned short g_Ah[ROWS * D_];        // attn out hi
__device__ __align__(16) unsigned short g_Al[ROWS * D_];        // attn out lo

// ---------------- helpers --------------------------------------------------
// paired split via cvt.rn.bf16x2 (RNE):
// H = bf16(v0) | bf16(v1)<<16 ; L = bf16(v0-hi0) | bf16(v1-hi1)<<16
__device__ __forceinline__ void split2(float v0, float v1, unsigned& H, unsigned& L) {
  asm("cvt.rn.bf16x2.f32 %0, %1, %2;" : "=r"(H) : "f"(v1), "f"(v0));
  float h0 = __uint_as_float(H << 16);
  float h1 = __uint_as_float(H & 0xFFFF0000u);
  float l0 = v0 - h0, l1 = v1 - h1;
  asm("cvt.rn.bf16x2.f32 %0, %1, %2;" : "=r"(L) : "f"(l1), "f"(l0));
}
__device__ __forceinline__ void mma16816(float* c, const unsigned* a,
                                         unsigned b0, unsigned b1) {
  asm volatile(
      "mma.sync.aligned.m16n8k16.row.col.f32.bf16.bf16.f32 "
      "{%0,%1,%2,%3}, {%4,%5,%6,%7}, {%8,%9}, {%0,%1,%2,%3};\n"
      : "+f"(c[0]), "+f"(c[1]), "+f"(c[2]), "+f"(c[3])
      : "r"(a[0]), "r"(a[1]), "r"(a[2]), "r"(a[3]), "r"(b0), "r"(b1));
}
__device__ __forceinline__ void ldsm4(unsigned* r, unsigned a) {
  asm volatile("ldmatrix.sync.aligned.m8n8.x4.shared.b16 {%0,%1,%2,%3}, [%4];\n"
               : "=r"(r[0]), "=r"(r[1]), "=r"(r[2]), "=r"(r[3]) : "r"(a));
}
__device__ __forceinline__ void ldsm4t(unsigned* r, unsigned a) {
  asm volatile("ldmatrix.sync.aligned.m8n8.x4.trans.shared.b16 {%0,%1,%2,%3}, [%4];\n"
               : "=r"(r[0]), "=r"(r[1]), "=r"(r[2]), "=r"(r[3]) : "r"(a));
}
__device__ __forceinline__ void cp16(void* smem, const void* gmem) {
  unsigned s = (unsigned)__cvta_generic_to_shared(smem);
  asm volatile("cp.async.cg.shared.global [%0], [%1], 16;\n" :: "r"(s), "l"(gmem));
}
#define CP_COMMIT() asm volatile("cp.async.commit_group;\n" ::: "memory")
#define CP_WAIT(n)  asm volatile("cp.async.wait_group %0;\n" :: "n"(n) : "memory")

// ---------------- pre-split: fp32 -> hi/lo bf16 ----------------------------
__global__ void split4(const float4* __restrict__ src, uint2* __restrict__ dh,
                       uint2* __restrict__ dl, int n4) {
  int i = blockIdx.x * blockDim.x + threadIdx.x;
  if (i >= n4) return;
  float4 v = src[i];
  unsigned H0, L0, H1, L1;
  split2(v.x, v.y, H0, L0);
  split2(v.z, v.w, H1, L1);
  dh[i] = make_uint2(H0, H1);
  dl[i] = make_uint2(L0, L1);
}

// ---------------------------------------------------------------------------
// Split-bf16 GEMM, CTA MTx128, warp tile (MT/2)x32, cp.async double-buffer +
// ldmatrix, term-major mma. MT=128 for GEMM1 (R12-proven), MT=64 for GEMM2
// (halved tiles -> 768 CTAs -> 2.59-wave packing instead of 1.3 waves of 2x).
// SMEM (u16): Ah[2][MT][40] | Al | Bh[2][32][136] | Bl
//   MT=128: 75,776 B ; MT=64: 55,296 B (both 2 CTA/SM)
// ---------------------------------------------------------------------------
template <int LDB, int MODE, int MT>
__global__ __launch_bounds__(256) void gemm_mma(
    const unsigned short* __restrict__ Agh, const unsigned short* __restrict__ Agl,
    const unsigned short* __restrict__ Bgh, const unsigned short* __restrict__ Bgl,
    const float* __restrict__ aux, float* __restrict__ C)
{
  constexpr int MI = MT / 32;              // m16 tiles per warp (4 or 2)
  constexpr int A_STG = MT * 40;           // u16 per A plane stage
  extern __shared__ __align__(16) unsigned short smem_u16[];
  const int tid = threadIdx.x, lane = tid & 31, warp = tid >> 5;
  const int g = lane >> 2, tg = lane & 3;
  const int wm = (warp >> 2) * (MT / 2), wn = (warp & 3) * 32;
  const int bx = blockIdx.x, by = blockIdx.y;

  float acc[MI][4][4] = {};

  const unsigned sbase = (unsigned)__cvta_generic_to_shared(smem_u16);
  const unsigned aoff = ((wm + (lane & 15)) * 40 + (lane >> 4) * 8) * 2;
  const unsigned boff = ((lane & 15) * 136 + wn + (lane >> 4) * 8) * 2;

  auto load_stage = [&](int k0, int st) {
    unsigned short* dAh = smem_u16 + st * A_STG;
    unsigned short* dAl = smem_u16 + 2 * A_STG + st * A_STG;
    unsigned short* dBh = smem_u16 + 4 * A_STG + st * 4352;
    unsigned short* dBl = smem_u16 + 4 * A_STG + 8704 + st * 4352;
#pragma unroll
    for (int t = 0; t < MT / 64; t++) {    // A: MT rows x 32 k
      int c = tid + t * 256;
      int ar = c >> 2, ak = (c & 3) * 8;
      size_t ga = (size_t)(by * MT + ar) * D_ + k0 + ak;
      cp16(dAh + ar * 40 + ak, Agh + ga);
      cp16(dAl + ar * 40 + ak, Agl + ga);
    }
    {
      int br = tid >> 4, bn = (tid & 15) * 8;
      size_t gb = (size_t)(k0 + br) * LDB + bx * 128 + bn;
      cp16(dBh + br * 136 + bn, Bgh + gb);
      cp16(dBl + br * 136 + bn, Bgl + gb);
      int c2 = tid + 256;
      int br2 = c2 >> 4, bn2 = (c2 & 15) * 8;
      size_t gb2 = (size_t)(k0 + br2) * LDB + bx * 128 + bn2;
      cp16(dBh + br2 * 136 + bn2, Bgh + gb2);
      cp16(dBl + br2 * 136 + bn2, Bgl + gb2);
    }
    CP_COMMIT();
  };

  load_stage(0, 0);
  for (int it = 0; it < 24; it++) {
    if (it + 1 < 24) {
      load_stage((it + 1) * 32, (it + 1) & 1);
      CP_WAIT(1);
    } else {
      CP_WAIT(0);
    }
    __syncthreads();
    const int st = it & 1;
    const unsigned sAh = sbase + st * (A_STG * 2);
    const unsigned sAl = sbase + 4 * A_STG + st * (A_STG * 2);
    const unsigned sBh = sbase + 8 * A_STG + st * 8704;
    const unsigned sBl = sbase + 8 * A_STG + 17408 + st * 8704;
#pragma unroll
    for (int kk = 0; kk < 2; kk++) {
      unsigned ah[MI][4], al[MI][4], bh[2][4], bl[2][4];
#pragma unroll
      for (int i = 0; i < MI; i++) {
        ldsm4(ah[i], sAh + aoff + i * 1280 + kk * 32);
        ldsm4(al[i], sAl + aoff + i * 1280 + kk * 32);
      }
#pragma unroll
      for (int jj = 0; jj < 2; jj++) {
        ldsm4t(bh[jj], sBh + boff + kk * 4352 + jj * 32);
        ldsm4t(bl[jj], sBl + boff + kk * 4352 + jj * 32);
      }
      // term-major: 3 passes over all accumulators
#pragma unroll
      for (int i = 0; i < MI; i++)
#pragma unroll
        for (int jj = 0; jj < 2; jj++) {
          mma16816(acc[i][2 * jj],     ah[i], bh[jj][0], bh[jj][1]);
          mma16816(acc[i][2 * jj + 1], ah[i], bh[jj][2], bh[jj][3]);
        }
#pragma unroll
      for (int i = 0; i < MI; i++)
#pragma unroll
        for (int jj = 0; jj < 2; jj++) {
          mma16816(acc[i][2 * jj],     ah[i], bl[jj][0], bl[jj][1]);
          mma16816(acc[i][2 * jj + 1], ah[i], bl[jj][2], bl[jj][3]);
        }
#pragma unroll
      for (int i = 0; i < MI; i++)
#pragma unroll
        for (int jj = 0; jj < 2; jj++) {
          mma16816(acc[i][2 * jj],     al[i], bh[jj][0], bh[jj][1]);
          mma16816(acc[i][2 * jj + 1], al[i], bh[jj][2], bh[jj][3]);
        }
    }
    __syncthreads();
  }

  if constexpr (MODE == 0) {
    const int which = bx / 6;   // 0=Q 1=K 2=V  (768 = 6 tiles of 128)
#pragma unroll
    for (int i = 0; i < MI; i++) {
#pragma unroll
      for (int half = 0; half < 2; half++) {
        const int m = by * MT + wm + i * 16 + g + half * 8;
        const float gate = aux[m];
        const int b = m >> 10, tok = m & 1023;
#pragma unroll
        for (int j = 0; j < 4; j++) {
          const int col = bx * 128 + wn + j * 8 + 2 * tg;
          const int dd = col - which * D_;
          const int h = dd >> 6, hd = dd & 63;
          const int bh = b * H_ + h;
          float v0 = acc[i][j][half * 2 + 0] * gate;
          float v1 = acc[i][j][half * 2 + 1] * gate;
          if (which == 0) { v0 *= SCALE_; v1 *= SCALE_; }
          unsigned Hv, Lv;
          split2(v0, v1, Hv, Lv);
          if (which == 0) {
            const size_t idx = ((size_t)bh * N_ + tok) * HD_ + hd;
            *reinterpret_cast<unsigned*>(&g_Qh[idx]) = Hv;
            *reinterpret_cast<unsigned*>(&g_Ql[idx]) = Lv;
          } else if (which == 1) {
            const size_t idx = ((size_t)bh * N_ + tok) * HD_ + hd;
            *reinterpret_cast<unsigned*>(&g_Kh[idx]) = Hv;
            *reinterpret_cast<unsigned*>(&g_Kl[idx]) = Lv;
          } else {
            const size_t r0 = ((size_t)bh * HD_ + hd) * N_ + tok;
            g_Vth[r0] = (unsigned short)Hv; g_Vth[r0 + N_] = (unsigned short)(Hv >> 16);
            g_Vtl[r0] = (unsigned short)Lv; g_Vtl[r0 + N_] = (unsigned short)(Lv >> 16);
          }
        }
      }
    }
  } else {
#pragma unroll
    for (int i = 0; i < MI; i++)
#pragma unroll
      for (int half = 0; half < 2; half++) {
        const int m = by * MT + wm + i * 16 + g + half * 8;
#pragma unroll
        for (int j = 0; j < 4; j++) {
          const int col = bx * 128 + wn + j * 8 + 2 * tg;
          float2 o;
          o.x = acc[i][j][half * 2 + 0] + aux[col];
          o.y = acc[i][j][half * 2 + 1] + aux[col + 1];
          *reinterpret_cast<float2*>(&C[(size_t)m * D_ + col]) = o;
        }
      }
  }
}

#define GEMM1_SMEM 75776
#define GEMM2_SMEM 55296

// ---------------------------------------------------------------------------
// Flash attention (byte-identical to R12 best): 128 queries/CTA, online
// softmax, S/P in registers, K->buf0 / V^T->buf1 cp.async ping-pong,
// interleaved mma, softmax emits fragment-ready bf16x2 hi/lo words.
// ---------------------------------------------------------------------------
#define FA_STG  36864
#define FA_LO   18432
#define FA_SMEM (2 * FA_STG)

__global__ __launch_bounds__(256, 1) void attn_flash()
{
  extern __shared__ __align__(16) unsigned short KV[];
  const unsigned kvb = (unsigned)__cvta_generic_to_shared(KV);

  const int tid = threadIdx.x, lane = tid & 31, warp = tid >> 5;
  const int g = lane >> 2, tg = lane & 3;
  const int bh = blockIdx.y;
  const int q0 = blockIdx.x * 128;
  const size_t kbase = (size_t)bh * N_ * HD_;
  const size_t vbase = (size_t)bh * HD_ * N_;
  const size_t qrow = kbase + (size_t)(q0 + warp * 16 + g) * HD_;

  auto load_k = [&](int kt) {
    unsigned short* dst = KV;
    const unsigned short* sh = g_Kh + kbase + (size_t)kt * 128 * HD_;
    const unsigned short* sl = g_Kl + kbase + (size_t)kt * 128 * HD_;
#pragma unroll
    for (int t = 0; t < 4; t++) {
      int c = tid + t * 256;
      int row = c >> 3, ko = (c & 7) * 8;
      cp16(dst + row * 72 + ko, sh + row * HD_ + ko);
      cp16(dst + 9216 + row * 72 + ko, sl + row * HD_ + ko);
    }
    CP_COMMIT();
  };
  auto load_v = [&](int vt) {
    unsigned short* dst = KV + 18432;
    const unsigned short* sh = g_Vth + vbase + vt * 128;
    const unsigned short* sl = g_Vtl + vbase + vt * 128;
#pragma unroll
    for (int t = 0; t < 4; t++) {
      int c = tid + t * 256;
      int row = c >> 4, no = (c & 15) * 8;
      cp16(dst + row * 136 + no, sh + (size_t)row * N_ + no);
      cp16(dst + 9216 + row * 136 + no, sl + (size_t)row * N_ + no);
    }
    CP_COMMIT();
  };

  load_k(0);
  load_v(0);

  unsigned qh[4][4], ql[4][4];
#pragma unroll
  for (int c = 0; c < 4; c++) {
    const size_t r0 = qrow + c * 16 + 2 * tg;
    const size_t r8 = r0 + 8 * HD_;
    qh[c][0] = *reinterpret_cast<const unsigned*>(&g_Qh[r0]);
    qh[c][1] = *reinterpret_cast<const unsigned*>(&g_Qh[r8]);
    qh[c][2] = *reinterpret_cast<const unsigned*>(&g_Qh[r0 + 8]);
    qh[c][3] = *reinterpret_cast<const unsigned*>(&g_Qh[r8 + 8]);
    ql[c][0] = *reinterpret_cast<const unsigned*>(&g_Ql[r0]);
    ql[c][1] = *reinterpret_cast<const unsigned*>(&g_Ql[r8]);
    ql[c][2] = *reinterpret_cast<const unsigned*>(&g_Ql[r0 + 8]);
    ql[c][3] = *reinterpret_cast<const unsigned*>(&g_Ql[r8 + 8]);
  }

  float oacc[8][4] = {};
  float m0 = -1e30f, m1 = -1e30f, l0 = 0.f, l1 = 0.f;

  const unsigned kfb = ((lane & 15) * 72 + (lane >> 4) * 8) * 2;
  const unsigned vfb = ((lane & 7) * 136 + (lane >> 3) * 8) * 2;

#pragma unroll 1
  for (int kt = 0; kt < 8; kt++) {
    // ---- S = Q K^T ----
    CP_WAIT(1);
    __syncthreads();
    float sacc[16][4] = {};
#pragma unroll
    for (int kg = 0; kg < 8; kg++) {
      const unsigned kb = kvb + kg * 2304 + kfb;
      unsigned kh[4][4], kl[4][4];
#pragma unroll
      for (int c = 0; c < 4; c++) {
        ldsm4(kh[c], kb + c * 32);
        ldsm4(kl[c], kb + FA_LO + c * 32);
      }
      float* s0 = sacc[2 * kg];
      float* s1 = sacc[2 * kg + 1];
#pragma unroll
      for (int c = 0; c < 4; c++) {
        mma16816(s0, qh[c], kh[c][0], kh[c][2]);
        mma16816(s1, qh[c], kh[c][1], kh[c][3]);
      }
#pragma unroll
      for (int c = 0; c < 4; c++) {
        mma16816(s0, qh[c], kl[c][0], kl[c][2]);
        mma16816(s1, qh[c], kl[c][1], kl[c][3]);
      }
#pragma unroll
      for (int c = 0; c < 4; c++) {
        mma16816(s0, ql[c], kh[c][0], kh[c][2]);
        mma16816(s1, ql[c], kh[c][1], kh[c][3]);
      }
    }
    __syncthreads();
    if (kt < 7) load_k(kt + 1);

    // ---- online softmax; emit fragment-ready bf16x2 hi/lo words ----
    float mx0 = -1e30f, mx1 = -1e30f;
#pragma unroll
    for (int t = 0; t < 16; t++) {
      mx0 = fmaxf(mx0, fmaxf(sacc[t][0], sacc[t][1]));
      mx1 = fmaxf(mx1, fmaxf(sacc[t][2], sacc[t][3]));
    }
    mx0 = fmaxf(mx0, __shfl_xor_sync(0xffffffffu, mx0, 1));
    mx0 = fmaxf(mx0, __shfl_xor_sync(0xffffffffu, mx0, 2));
    mx1 = fmaxf(mx1, __shfl_xor_sync(0xffffffffu, mx1, 1));
    mx1 = fmaxf(mx1, __shfl_xor_sync(0xffffffffu, mx1, 2));
    const float m0n = fmaxf(m0, mx0), m1n = fmaxf(m1, mx1);
    const float c0 = __expf(m0 - m0n), c1 = __expf(m1 - m1n);
    m0 = m0n; m1 = m1n;
    float ts0 = 0.f, ts1 = 0.f;
#pragma unroll
    for (int t = 0; t < 16; t++) {
      float p0 = __expf(sacc[t][0] - m0n), p1 = __expf(sacc[t][1] - m0n);
      float p2 = __expf(sacc[t][2] - m1n), p3 = __expf(sacc[t][3] - m1n);
      ts0 += p0 + p1; ts1 += p2 + p3;
      unsigned H01, L01, H23, L23;
      split2(p0, p1, H01, L01);
      split2(p2, p3, H23, L23);
      sacc[t][0] = __uint_as_float(H01);
      sacc[t][1] = __uint_as_float(L01);
      sacc[t][2] = __uint_as_float(H23);
      sacc[t][3] = __uint_as_float(L23);
    }
    ts0 += __shfl_xor_sync(0xffffffffu, ts0, 1);
    ts0 += __shfl_xor_sync(0xffffffffu, ts0, 2);
    ts1 += __shfl_xor_sync(0xffffffffu, ts1, 1);
    ts1 += __shfl_xor_sync(0xffffffffu, ts1, 2);
    l0 = l0 * c0 + ts0;
    l1 = l1 * c1 + ts1;
#pragma unroll
    for (int vn = 0; vn < 8; vn++) {
      oacc[vn][0] *= c0; oacc[vn][1] *= c0;
      oacc[vn][2] *= c1; oacc[vn][3] *= c1;
    }

    // ---- O += P V ----
    CP_WAIT(1);
    if (kt == 7) CP_WAIT(0);
    __syncthreads();
#pragma unroll
    for (int tt = 0; tt < 4; tt++) {
      unsigned pfh[2][4], pfl[2][4];
#pragma unroll
      for (int cc = 0; cc < 2; cc++) {
        const int t0 = (2 * tt + cc) * 2;
        pfh[cc][0] = __float_as_uint(sacc[t0][0]);
        pfh[cc][1] = __float_as_uint(sacc[t0][2]);
        pfh[cc][2] = __float_as_uint(sacc[t0 + 1][0]);
        pfh[cc][3] = __float_as_uint(sacc[t0 + 1][2]);
        pfl[cc][0] = __float_as_uint(sacc[t0][1]);
        pfl[cc][1] = __float_as_uint(sacc[t0][3]);
        pfl[cc][2] = __float_as_uint(sacc[t0 + 1][1]);
        pfl[cc][3] = __float_as_uint(sacc[t0 + 1][3]);
      }
#pragma unroll
      for (int vp = 0; vp < 4; vp++) {
        const int vn0 = 2 * vp, vn1 = 2 * vp + 1;
        const unsigned vb0 = kvb + FA_STG + vn0 * 2176 + vfb + tt * 64;
        const unsigned vb1 = kvb + FA_STG + vn1 * 2176 + vfb + tt * 64;
        unsigned vh0[4], vl0[4], vh1[4], vl1[4];
        ldsm4(vh0, vb0);
        ldsm4(vl0, vb0 + FA_LO);
        ldsm4(vh1, vb1);
        ldsm4(vl1, vb1 + FA_LO);
        float* o0 = oacc[vn0];
        float* o1 = oacc[vn1];
        mma16816(o0, pfh[0], vh0[0], vh0[1]);
        mma16816(o1, pfh[0], vh1[0], vh1[1]);
        mma16816(o0, pfh[0], vl0[0], vl0[1]);
        mma16816(o1, pfh[0], vl1[0], vl1[1]);
        mma16816(o0, pfl[0], vh0[0], vh0[1]);
        mma16816(o1, pfl[0], vh1[0], vh1[1]);
        mma16816(o0, pfh[1], vh0[2], vh0[3]);
        mma16816(o1, pfh[1], vh1[2], vh1[3]);
        mma16816(o0, pfh[1], vl0[2], vl0[3]);
        mma16816(o1, pfh[1], vl1[2], vl1[3]);
        mma16816(o0, pfl[1], vh0[2], vh0[3]);
        mma16816(o1, pfl[1], vh1[2], vh1[3]);
      }
    }
    __syncthreads();
    if (kt < 7) load_v(kt + 1);
  }

  // ---- finalize: normalize, write split bf16 O for GEMM2 ----
  const float inv0 = 1.f / l0, inv1 = 1.f / l1;
  const int b = bh / H_, h = bh - (bh / H_) * H_;
  const int tok = q0 + warp * 16 + g;
  const size_t base0 = (size_t)(b * N_ + tok) * D_ + h * HD_ + 2 * tg;
  const size_t base8 = base0 + (size_t)8 * D_;
#pragma unroll
  for (int vn = 0; vn < 8; vn++) {
    unsigned Hv, Lv;
    split2(oacc[vn][0] * inv0, oacc[vn][1] * inv0, Hv, Lv);
    *reinterpret_cast<unsigned*>(&g_Ah[base0 + vn * 8]) = Hv;
    *reinterpret_cast<unsigned*>(&g_Al[base0 + vn * 8]) = Lv;
    split2(oacc[vn][2] * inv1, oacc[vn][3] * inv1, Hv, Lv);
    *reinterpret_cast<unsigned*>(&g_Ah[base8 + vn * 8]) = Hv;
    *reinterpret_cast<unsigned*>(&g_Al[base8 + vn * 8]) = Lv;
  }
}

// ---------------------------------------------------------------------------
extern "C" void kernel_launch(void* const* d_in, const int* in_sizes, int n_in,
                              void* d_out, int out_size)
{
  const float* x      = (const float*)d_in[0];
  const float* weight = (const float*)d_in[1];
  const float* W_qkv  = (const float*)d_in[2];
  const float* W_msa  = (const float*)d_in[3];
  const float* b_msa  = (const float*)d_in[4];
  float* out = (float*)d_out;

  unsigned short *xh, *xl, *wqh, *wql, *wmh, *wml, *ah, *al;
  cudaGetSymbolAddress((void**)&xh,  g_Xh);  cudaGetSymbolAddress((void**)&xl,  g_Xl);
  cudaGetSymbolAddress((void**)&wqh, g_Wqh); cudaGetSymbolAddress((void**)&wql, g_Wql);
  cudaGetSymbolAddress((void**)&wmh, g_Wmh); cudaGetSymbolAddress((void**)&wml, g_Wml);
  cudaGetSymbolAddress((void**)&ah,  g_Ah);  cudaGetSymbolAddress((void**)&al,  g_Al);

  cudaFuncSetAttribute((const void*)gemm_mma<D3_, 0, 128>,
                       cudaFuncAttributeMaxDynamicSharedMemorySize, GEMM1_SMEM);
  cudaFuncSetAttribute((const void*)gemm_mma<D_, 1, 64>,
                       cudaFuncAttributeMaxDynamicSharedMemorySize, GEMM2_SMEM);
  cudaFuncSetAttribute(attn_flash,
                       cudaFuncAttributeMaxDynamicSharedMemorySize, FA_SMEM);

  split4<<<ROWS * D_ / 4 / 256, 256>>>((const float4*)x, (uint2*)xh, (uint2*)xl,
                                       ROWS * D_ / 4);
  split4<<<D_ * D3_ / 4 / 256, 256>>>((const float4*)W_qkv, (uint2*)wqh, (uint2*)wql,
                                      D_ * D3_ / 4);
  split4<<<D_ * D_ / 4 / 256, 256>>>((const float4*)W_msa, (uint2*)wmh, (uint2*)wml,
                                     D_ * D_ / 4);
  gemm_mma<D3_, 0, 128><<<dim3(D3_ / 128, ROWS / 128), 256, GEMM1_SMEM>>>(
      xh, xl, wqh, wql, weight, nullptr);
  attn_flash<<<dim3(N_ / 128, NBH), 256, FA_SMEM>>>();
  gemm_mma<D_, 1, 64><<<dim3(D_ / 128, ROWS / 64), 256, GEMM2_SMEM>>>(
      ah, al, wmh, wml, b_msa, out);
}

// round 15
// speedup vs baseline: 1.5086x; 1.3997x over previous
#include <cuda_runtime.h>
#include <cuda_fp16.h>

#define B_   8
#define N_   1024
#define D_   768
#define H_   12
#define HD_  64
#define ROWS (B_ * N_)      // 8192
#define D3_  (3 * D_)       // 2304
#define SCALE_ 0.125f
#define NBH  (B_ * H_)      // 96

// ---------------- fp16 scratch (alloc-free rule: device globals) -----------
// A-side tensors: plain fp16. B-side tensors: split fp16 (hi + residual lo).
__device__ __align__(16) unsigned short g_Xf[ROWS * D_];        // x plain
__device__ __align__(16) unsigned short g_Wqh[D_ * D3_];
__device__ __align__(16) unsigned short g_Wql[D_ * D3_];
__device__ __align__(16) unsigned short g_Wmh[D_ * D_];
__device__ __align__(16) unsigned short g_Wml[D_ * D_];
__device__ __align__(16) unsigned short g_Qf[NBH * N_ * HD_];   // Q plain
__device__ __align__(16) unsigned short g_Kh[NBH * N_ * HD_];
__device__ __align__(16) unsigned short g_Kl[NBH * N_ * HD_];
__device__ __align__(16) unsigned short g_Vth[NBH * HD_ * N_];  // [bh][hd][key]
__device__ __align__(16) unsigned short g_Vtl[NBH * HD_ * N_];
__device__ __align__(16) unsigned short g_Af[ROWS * D_];        // attn out plain

// ---------------- helpers --------------------------------------------------
// pack two fp32 -> fp16x2 word (v0 low, v1 high), RNE
__device__ __forceinline__ unsigned pack2h(float v0, float v1) {
  unsigned H;
  asm("cvt.rn.f16x2.f32 %0, %1, %2;" : "=r"(H) : "f"(v1), "f"(v0));
  return H;
}
// paired fp16 split: H = h(v0)|h(v1)<<16 ; L = h(v0-h0)|h(v1-h1)<<16
__device__ __forceinline__ void split2h(float v0, float v1, unsigned& H, unsigned& L) {
  asm("cvt.rn.f16x2.f32 %0, %1, %2;" : "=r"(H) : "f"(v1), "f"(v0));
  __half2 t;
  *reinterpret_cast<unsigned*>(&t) = H;
  float l0 = v0 - __low2float(t);
  float l1 = v1 - __high2float(t);
  asm("cvt.rn.f16x2.f32 %0, %1, %2;" : "=r"(L) : "f"(l1), "f"(l0));
}
__device__ __forceinline__ void mmah(float* c, const unsigned* a,
                                     unsigned b0, unsigned b1) {
  asm volatile(
      "mma.sync.aligned.m16n8k16.row.col.f32.f16.f16.f32 "
      "{%0,%1,%2,%3}, {%4,%5,%6,%7}, {%8,%9}, {%0,%1,%2,%3};\n"
      : "+f"(c[0]), "+f"(c[1]), "+f"(c[2]), "+f"(c[3])
      : "r"(a[0]), "r"(a[1]), "r"(a[2]), "r"(a[3]), "r"(b0), "r"(b1));
}
__device__ __forceinline__ void ldsm4(unsigned* r, unsigned a) {
  asm volatile("ldmatrix.sync.aligned.m8n8.x4.shared.b16 {%0,%1,%2,%3}, [%4];\n"
               : "=r"(r[0]), "=r"(r[1]), "=r"(r[2]), "=r"(r[3]) : "r"(a));
}
__device__ __forceinline__ void ldsm4t(unsigned* r, unsigned a) {
  asm volatile("ldmatrix.sync.aligned.m8n8.x4.trans.shared.b16 {%0,%1,%2,%3}, [%4];\n"
               : "=r"(r[0]), "=r"(r[1]), "=r"(r[2]), "=r"(r[3]) : "r"(a));
}
__device__ __forceinline__ void cp16(void* smem, const void* gmem) {
  unsigned s = (unsigned)__cvta_generic_to_shared(smem);
  asm volatile("cp.async.cg.shared.global [%0], [%1], 16;\n" :: "r"(s), "l"(gmem));
}
#define CP_COMMIT() asm volatile("cp.async.commit_group;\n" ::: "memory")
#define CP_WAIT(n)  asm volatile("cp.async.wait_group %0;\n" :: "n"(n) : "memory")

// ---------------- pre-pass: fp32 -> fp16 (plain / split) -------------------
__global__ void conv4(const float4* __restrict__ src, uint2* __restrict__ d, int n4) {
  int i = blockIdx.x * blockDim.x + threadIdx.x;
  if (i >= n4) return;
  float4 v = src[i];
  d[i] = make_uint2(pack2h(v.x, v.y), pack2h(v.z, v.w));
}
__global__ void split4h(const float4* __restrict__ src, uint2* __restrict__ dh,
                        uint2* __restrict__ dl, int n4) {
  int i = blockIdx.x * blockDim.x + threadIdx.x;
  if (i >= n4) return;
  float4 v = src[i];
  unsigned H0, L0, H1, L1;
  split2h(v.x, v.y, H0, L0);
  split2h(v.z, v.w, H1, L1);
  dh[i] = make_uint2(H0, H1);
  dl[i] = make_uint2(L0, L1);
}

// ---------------------------------------------------------------------------
// Asymmetric fp16 GEMM: A plain fp16, B split fp16, 2 mma per k16 chunk.
// CTA 128x128, kstep 32, 8 warps (2m x 4n), warp tile 64x32, 2 CTA/SM.
// SMEM (u16): A[2][128][40] @0 | Bh[2][32][136] @10240 | Bl @18944
// total 27648 u16 = 55,296 B.
// MODE 0: epilogue gate+scale -> Q plain / K split / V^T split.
// MODE 1: epilogue + bias -> fp32 C.
// ---------------------------------------------------------------------------
#define GEMM_SMEM 55296

template <int LDB, int MODE>
__global__ __launch_bounds__(256) void gemm_mma(
    const unsigned short* __restrict__ Af,
    const unsigned short* __restrict__ Bgh, const unsigned short* __restrict__ Bgl,
    const float* __restrict__ aux, float* __restrict__ C)
{
  extern __shared__ __align__(16) unsigned short smem_u16[];
  const int tid = threadIdx.x, lane = tid & 31, warp = tid >> 5;
  const int g = lane >> 2, tg = lane & 3;
  const int wm = (warp >> 2) * 64, wn = (warp & 3) * 32;
  const int bx = blockIdx.x, by = blockIdx.y;

  float acc[4][4][4] = {};

  const unsigned sbase = (unsigned)__cvta_generic_to_shared(smem_u16);
  const unsigned aoff = ((wm + (lane & 15)) * 40 + (lane >> 4) * 8) * 2;
  const unsigned boff = ((lane & 15) * 136 + wn + (lane >> 4) * 8) * 2;

  auto load_stage = [&](int k0, int st) {
    unsigned short* dA  = smem_u16 + st * 5120;
    unsigned short* dBh = smem_u16 + 10240 + st * 4352;
    unsigned short* dBl = smem_u16 + 18944 + st * 4352;
#pragma unroll
    for (int t = 0; t < 2; t++) {
      int c = tid + t * 256;
      int ar = c >> 2, ak = (c & 3) * 8;
      cp16(dA + ar * 40 + ak, Af + (size_t)(by * 128 + ar) * D_ + k0 + ak);
      int br = c >> 4, bn = (c & 15) * 8;
      size_t gb = (size_t)(k0 + br) * LDB + bx * 128 + bn;
      cp16(dBh + br * 136 + bn, Bgh + gb);
      cp16(dBl + br * 136 + bn, Bgl + gb);
    }
    CP_COMMIT();
  };

  load_stage(0, 0);
  for (int it = 0; it < 24; it++) {
    if (it + 1 < 24) {
      load_stage((it + 1) * 32, (it + 1) & 1);
      CP_WAIT(1);
    } else {
      CP_WAIT(0);
    }
    __syncthreads();
    const int st = it & 1;
    const unsigned sA  = sbase + st * 10240;
    const unsigned sBh = sbase + 20480 + st * 8704;
    const unsigned sBl = sbase + 37888 + st * 8704;
#pragma unroll
    for (int kk = 0; kk < 2; kk++) {
      unsigned af[4][4], bh[2][4], bl[2][4];
#pragma unroll
      for (int i = 0; i < 4; i++)
        ldsm4(af[i], sA + aoff + i * 1280 + kk * 32);
#pragma unroll
      for (int jj = 0; jj < 2; jj++) {
        ldsm4t(bh[jj], sBh + boff + kk * 4352 + jj * 32);
        ldsm4t(bl[jj], sBl + boff + kk * 4352 + jj * 32);
      }
      // 2 term-major passes over 16 accumulators
#pragma unroll
      for (int i = 0; i < 4; i++)
#pragma unroll
        for (int jj = 0; jj < 2; jj++) {
          mmah(acc[i][2 * jj],     af[i], bh[jj][0], bh[jj][1]);
          mmah(acc[i][2 * jj + 1], af[i], bh[jj][2], bh[jj][3]);
        }
#pragma unroll
      for (int i = 0; i < 4; i++)
#pragma unroll
        for (int jj = 0; jj < 2; jj++) {
          mmah(acc[i][2 * jj],     af[i], bl[jj][0], bl[jj][1]);
          mmah(acc[i][2 * jj + 1], af[i], bl[jj][2], bl[jj][3]);
        }
    }
    __syncthreads();
  }

  if constexpr (MODE == 0) {
    const int which = bx / 6;   // 0=Q 1=K 2=V
#pragma unroll
    for (int i = 0; i < 4; i++) {
#pragma unroll
      for (int half = 0; half < 2; half++) {
        const int m = by * 128 + wm + i * 16 + g + half * 8;
        const float gate = aux[m];
        const int b = m >> 10, tok = m & 1023;
#pragma unroll
        for (int j = 0; j < 4; j++) {
          const int col = bx * 128 + wn + j * 8 + 2 * tg;
          const int dd = col - which * D_;
          const int h = dd >> 6, hd = dd & 63;
          const int bh = b * H_ + h;
          float v0 = acc[i][j][half * 2 + 0] * gate;
          float v1 = acc[i][j][half * 2 + 1] * gate;
          if (which == 0) {
            v0 *= SCALE_; v1 *= SCALE_;
            const size_t idx = ((size_t)bh * N_ + tok) * HD_ + hd;
            *reinterpret_cast<unsigned*>(&g_Qf[idx]) = pack2h(v0, v1);
          } else if (which == 1) {
            unsigned Hv, Lv;
            split2h(v0, v1, Hv, Lv);
            const size_t idx = ((size_t)bh * N_ + tok) * HD_ + hd;
            *reinterpret_cast<unsigned*>(&g_Kh[idx]) = Hv;
            *reinterpret_cast<unsigned*>(&g_Kl[idx]) = Lv;
          } else {
            unsigned Hv, Lv;
            split2h(v0, v1, Hv, Lv);
            const size_t r0 = ((size_t)bh * HD_ + hd) * N_ + tok;
            g_Vth[r0] = (unsigned short)Hv; g_Vth[r0 + N_] = (unsigned short)(Hv >> 16);
            g_Vtl[r0] = (unsigned short)Lv; g_Vtl[r0 + N_] = (unsigned short)(Lv >> 16);
          }
        }
      }
    }
  } else {
#pragma unroll
    for (int i = 0; i < 4; i++)
#pragma unroll
      for (int half = 0; half < 2; half++) {
        const int m = by * 128 + wm + i * 16 + g + half * 8;
#pragma unroll
        for (int j = 0; j < 4; j++) {
          const int col = bx * 128 + wn + j * 8 + 2 * tg;
          float2 o;
          o.x = acc[i][j][half * 2 + 0] + aux[col];
          o.y = acc[i][j][half * 2 + 1] + aux[col + 1];
          *reinterpret_cast<float2*>(&C[(size_t)m * D_ + col]) = o;
        }
      }
  }
}

// ---------------------------------------------------------------------------
// Flash attention, asymmetric fp16: Q plain (A), K/V split (B), 2 mma/chunk.
// 128 queries/CTA, online softmax, S/P in registers, K->buf0 / V^T->buf1
// cp.async ping-pong. Softmax emits plain-fp16 fragment words for P.
// ---------------------------------------------------------------------------
#define FA_STG  36864
#define FA_LO   18432
#define FA_SMEM (2 * FA_STG)

__global__ __launch_bounds__(256, 1) void attn_flash()
{
  extern __shared__ __align__(16) unsigned short KV[];
  const unsigned kvb = (unsigned)__cvta_generic_to_shared(KV);

  const int tid = threadIdx.x, lane = tid & 31, warp = tid >> 5;
  const int g = lane >> 2, tg = lane & 3;
  const int bh = blockIdx.y;
  const int q0 = blockIdx.x * 128;
  const size_t kbase = (size_t)bh * N_ * HD_;
  const size_t vbase = (size_t)bh * HD_ * N_;
  const size_t qrow = kbase + (size_t)(q0 + warp * 16 + g) * HD_;

  auto load_k = [&](int kt) {
    unsigned short* dst = KV;
    const unsigned short* sh = g_Kh + kbase + (size_t)kt * 128 * HD_;
    const unsigned short* sl = g_Kl + kbase + (size_t)kt * 128 * HD_;
#pragma unroll
    for (int t = 0; t < 4; t++) {
      int c = tid + t * 256;
      int row = c >> 3, ko = (c & 7) * 8;
      cp16(dst + row * 72 + ko, sh + row * HD_ + ko);
      cp16(dst + 9216 + row * 72 + ko, sl + row * HD_ + ko);
    }
    CP_COMMIT();
  };
  auto load_v = [&](int vt) {
    unsigned short* dst = KV + 18432;
    const unsigned short* sh = g_Vth + vbase + vt * 128;
    const unsigned short* sl = g_Vtl + vbase + vt * 128;
#pragma unroll
    for (int t = 0; t < 4; t++) {
      int c = tid + t * 256;
      int row = c >> 4, no = (c & 15) * 8;
      cp16(dst + row * 136 + no, sh + (size_t)row * N_ + no);
      cp16(dst + 9216 + row * 136 + no, sl + (size_t)row * N_ + no);
    }
    CP_COMMIT();
  };

  load_k(0);
  load_v(0);

  // resident Q fragments: plain fp16, 4 k16 chunks
  unsigned qf[4][4];
#pragma unroll
  for (int c = 0; c < 4; c++) {
    const size_t r0 = qrow + c * 16 + 2 * tg;
    const size_t r8 = r0 + 8 * HD_;
    qf[c][0] = *reinterpret_cast<const unsigned*>(&g_Qf[r0]);
    qf[c][1] = *reinterpret_cast<const unsigned*>(&g_Qf[r8]);
    qf[c][2] = *reinterpret_cast<const unsigned*>(&g_Qf[r0 + 8]);
    qf[c][3] = *reinterpret_cast<const unsigned*>(&g_Qf[r8 + 8]);
  }

  float oacc[8][4] = {};
  float m0 = -1e30f, m1 = -1e30f, l0 = 0.f, l1 = 0.f;

  const unsigned kfb = ((lane & 15) * 72 + (lane >> 4) * 8) * 2;
  const unsigned vfb = ((lane & 7) * 136 + (lane >> 3) * 8) * 2;

#pragma unroll 1
  for (int kt = 0; kt < 8; kt++) {
    // ---- S = Q K^T (2 term passes) ----
    CP_WAIT(1);
    __syncthreads();
    float sacc[16][4] = {};
#pragma unroll
    for (int kg = 0; kg < 8; kg++) {
      const unsigned kb = kvb + kg * 2304 + kfb;
      unsigned kh[4][4], kl[4][4];
#pragma unroll
      for (int c = 0; c < 4; c++) {
        ldsm4(kh[c], kb + c * 32);
        ldsm4(kl[c], kb + FA_LO + c * 32);
      }
      float* s0 = sacc[2 * kg];
      float* s1 = sacc[2 * kg + 1];
#pragma unroll
      for (int c = 0; c < 4; c++) {
        mmah(s0, qf[c], kh[c][0], kh[c][2]);
        mmah(s1, qf[c], kh[c][1], kh[c][3]);
      }
#pragma unroll
      for (int c = 0; c < 4; c++) {
        mmah(s0, qf[c], kl[c][0], kl[c][2]);
        mmah(s1, qf[c], kl[c][1], kl[c][3]);
      }
    }
    __syncthreads();
    if (kt < 7) load_k(kt + 1);

    // ---- online softmax; emit plain-fp16 P fragment words ----
    float mx0 = -1e30f, mx1 = -1e30f;
#pragma unroll
    for (int t = 0; t < 16; t++) {
      mx0 = fmaxf(mx0, fmaxf(sacc[t][0], sacc[t][1]));
      mx1 = fmaxf(mx1, fmaxf(sacc[t][2], sacc[t][3]));
    }
    mx0 = fmaxf(mx0, __shfl_xor_sync(0xffffffffu, mx0, 1));
    mx0 = fmaxf(mx0, __shfl_xor_sync(0xffffffffu, mx0, 2));
    mx1 = fmaxf(mx1, __shfl_xor_sync(0xffffffffu, mx1, 1));
    mx1 = fmaxf(mx1, __shfl_xor_sync(0xffffffffu, mx1, 2));
    const float m0n = fmaxf(m0, mx0), m1n = fmaxf(m1, mx1);
    const float c0 = __expf(m0 - m0n), c1 = __expf(m1 - m1n);
    m0 = m0n; m1 = m1n;
    float ts0 = 0.f, ts1 = 0.f;
#pragma unroll
    for (int t = 0; t < 16; t++) {
      float p0 = __expf(sacc[t][0] - m0n), p1 = __expf(sacc[t][1] - m0n);
      float p2 = __expf(sacc[t][2] - m1n), p3 = __expf(sacc[t][3] - m1n);
      ts0 += p0 + p1; ts1 += p2 + p3;
      sacc[t][0] = __uint_as_float(pack2h(p0, p1));   // rows g pair
      sacc[t][2] = __uint_as_float(pack2h(p2, p3));   // rows g+8 pair
    }
    ts0 += __shfl_xor_sync(0xffffffffu, ts0, 1);
    ts0 += __shfl_xor_sync(0xffffffffu, ts0, 2);
    ts1 += __shfl_xor_sync(0xffffffffu, ts1, 1);
    ts1 += __shfl_xor_sync(0xffffffffu, ts1, 2);
    l0 = l0 * c0 + ts0;
    l1 = l1 * c1 + ts1;
#pragma unroll
    for (int vn = 0; vn < 8; vn++) {
      oacc[vn][0] *= c0; oacc[vn][1] *= c0;
      oacc[vn][2] *= c1; oacc[vn][3] *= c1;
    }

    // ---- O += P V (2 term passes) ----
    CP_WAIT(1);
    if (kt == 7) CP_WAIT(0);
    __syncthreads();
#pragma unroll
    for (int tt = 0; tt < 4; tt++) {
      unsigned pf[2][4];
#pragma unroll
      for (int cc = 0; cc < 2; cc++) {
        const int t0 = (2 * tt + cc) * 2;
        pf[cc][0] = __float_as_uint(sacc[t0][0]);
        pf[cc][1] = __float_as_uint(sacc[t0][2]);
        pf[cc][2] = __float_as_uint(sacc[t0 + 1][0]);
        pf[cc][3] = __float_as_uint(sacc[t0 + 1][2]);
      }
#pragma unroll
      for (int vp = 0; vp < 4; vp++) {
        const int vn0 = 2 * vp, vn1 = 2 * vp + 1;
        const unsigned vb0 = kvb + FA_STG + vn0 * 2176 + vfb + tt * 64;
        const unsigned vb1 = kvb + FA_STG + vn1 * 2176 + vfb + tt * 64;
        unsigned vh0[4], vl0[4], vh1[4], vl1[4];
        ldsm4(vh0, vb0);
        ldsm4(vl0, vb0 + FA_LO);
        ldsm4(vh1, vb1);
        ldsm4(vl1, vb1 + FA_LO);
        float* o0 = oacc[vn0];
        float* o1 = oacc[vn1];
        mmah(o0, pf[0], vh0[0], vh0[1]);
        mmah(o1, pf[0], vh1[0], vh1[1]);
        mmah(o0, pf[0], vl0[0], vl0[1]);
        mmah(o1, pf[0], vl1[0], vl1[1]);
        mmah(o0, pf[1], vh0[2], vh0[3]);
        mmah(o1, pf[1], vh1[2], vh1[3]);
        mmah(o0, pf[1], vl0[2], vl0[3]);
        mmah(o1, pf[1], vl1[2], vl1[3]);
      }
    }
    __syncthreads();
    if (kt < 7) load_v(kt + 1);
  }

  // ---- finalize: normalize, write plain fp16 O (A-side of GEMM2) ----
  const float inv0 = 1.f / l0, inv1 = 1.f / l1;
  const int b = bh / H_, h = bh - (bh / H_) * H_;
  const int tok = q0 + warp * 16 + g;
  const size_t base0 = (size_t)(b * N_ + tok) * D_ + h * HD_ + 2 * tg;
  const size_t base8 = base0 + (size_t)8 * D_;
#pragma unroll
  for (int vn = 0; vn < 8; vn++) {
    *reinterpret_cast<unsigned*>(&g_Af[base0 + vn * 8]) =
        pack2h(oacc[vn][0] * inv0, oacc[vn][1] * inv0);
    *reinterpret_cast<unsigned*>(&g_Af[base8 + vn * 8]) =
        pack2h(oacc[vn][2] * inv1, oacc[vn][3] * inv1);
  }
}

// ---------------------------------------------------------------------------
extern "C" void kernel_launch(void* const* d_in, const int* in_sizes, int n_in,
                              void* d_out, int out_size)
{
  const float* x      = (const float*)d_in[0];
  const float* weight = (const float*)d_in[1];
  const float* W_qkv  = (const float*)d_in[2];
  const float* W_msa  = (const float*)d_in[3];
  const float* b_msa  = (const float*)d_in[4];
  float* out = (float*)d_out;

  unsigned short *xf, *wqh, *wql, *wmh, *wml, *af;
  cudaGetSymbolAddress((void**)&xf,  g_Xf);
  cudaGetSymbolAddress((void**)&wqh, g_Wqh); cudaGetSymbolAddress((void**)&wql, g_Wql);
  cudaGetSymbolAddress((void**)&wmh, g_Wmh); cudaGetSymbolAddress((void**)&wml, g_Wml);
  cudaGetSymbolAddress((void**)&af,  g_Af);

  cudaFuncSetAttribute(gemm_mma<D3_, 0>,
                       cudaFuncAttributeMaxDynamicSharedMemorySize, GEMM_SMEM);
  cudaFuncSetAttribute(gemm_mma<D_, 1>,
                       cudaFuncAttributeMaxDynamicSharedMemorySize, GEMM_SMEM);
  cudaFuncSetAttribute(attn_flash,
                       cudaFuncAttributeMaxDynamicSharedMemorySize, FA_SMEM);

  // 0) pre-pass: x -> plain fp16; weights -> split fp16
  conv4<<<ROWS * D_ / 4 / 256, 256>>>((const float4*)x, (uint2*)xf, ROWS * D_ / 4);
  split4h<<<D_ * D3_ / 4 / 256, 256>>>((const float4*)W_qkv, (uint2*)wqh, (uint2*)wql,
                                       D_ * D3_ / 4);
  split4h<<<D_ * D_ / 4 / 256, 256>>>((const float4*)W_msa, (uint2*)wmh, (uint2*)wml,
                                      D_ * D_ / 4);
  // 1) QKV projection + gate + head-major scatter
  gemm_mma<D3_, 0><<<dim3(D3_ / 128, ROWS / 128), 256, GEMM_SMEM>>>(
      xf, wqh, wql, weight, nullptr);
  // 2) flash attention
  attn_flash<<<dim3(N_ / 128, NBH), 256, FA_SMEM>>>();
  // 3) output projection + bias
  gemm_mma<D_, 1><<<dim3(D_ / 128, ROWS / 128), 256, GEMM_SMEM>>>(
      af, wmh, wml, b_msa, out);
}

// round 17
// speedup vs baseline: 2.4014x; 1.5918x over previous
#include <cuda_runtime.h>
#include <cuda_fp16.h>

#define B_   8
#define N_   1024
#define D_   768
#define H_   12
#define HD_  64
#define ROWS (B_ * N_)      // 8192
#define D3_  (3 * D_)       // 2304
#define SCALE_ 0.125f
#define NBH  (B_ * H_)      // 96

// ---------------- fp16 scratch (alloc-free rule: device globals) -----------
__device__ __align__(16) unsigned short g_Xf[ROWS * D_];        // x
__device__ __align__(16) unsigned short g_Wq[D_ * D3_];         // W_qkv
__device__ __align__(16) unsigned short g_Wm[D_ * D_];          // W_msa
__device__ __align__(16) unsigned short g_Qf[NBH * N_ * HD_];   // Q (scaled)
__device__ __align__(16) unsigned short g_Kf[NBH * N_ * HD_];   // K
__device__ __align__(16) unsigned short g_Vt[NBH * HD_ * N_];   // V^T [bh][hd][key]
__device__ __align__(16) unsigned short g_Af[ROWS * D_];        // attn out

// ---------------- helpers --------------------------------------------------
__device__ __forceinline__ unsigned pack2h(float v0, float v1) {
  unsigned H;
  asm("cvt.rn.f16x2.f32 %0, %1, %2;" : "=r"(H) : "f"(v1), "f"(v0));
  return H;
}
__device__ __forceinline__ void mmah(float* c, const unsigned* a,
                                     unsigned b0, unsigned b1) {
  asm volatile(
      "mma.sync.aligned.m16n8k16.row.col.f32.f16.f16.f32 "
      "{%0,%1,%2,%3}, {%4,%5,%6,%7}, {%8,%9}, {%0,%1,%2,%3};\n"
      : "+f"(c[0]), "+f"(c[1]), "+f"(c[2]), "+f"(c[3])
      : "r"(a[0]), "r"(a[1]), "r"(a[2]), "r"(a[3]), "r"(b0), "r"(b1));
}
__device__ __forceinline__ void ldsm4(unsigned* r, unsigned a) {
  asm volatile("ldmatrix.sync.aligned.m8n8.x4.shared.b16 {%0,%1,%2,%3}, [%4];\n"
               : "=r"(r[0]), "=r"(r[1]), "=r"(r[2]), "=r"(r[3]) : "r"(a));
}
__device__ __forceinline__ void ldsm4t(unsigned* r, unsigned a) {
  asm volatile("ldmatrix.sync.aligned.m8n8.x4.trans.shared.b16 {%0,%1,%2,%3}, [%4];\n"
               : "=r"(r[0]), "=r"(r[1]), "=r"(r[2]), "=r"(r[3]) : "r"(a));
}
__device__ __forceinline__ void cp16(void* smem, const void* gmem) {
  unsigned s = (unsigned)__cvta_generic_to_shared(smem);
  asm volatile("cp.async.cg.shared.global [%0], [%1], 16;\n" :: "r"(s), "l"(gmem));
}
#define CP_COMMIT() asm volatile("cp.async.commit_group;\n" ::: "memory")
#define CP_WAIT(n)  asm volatile("cp.async.wait_group %0;\n" :: "n"(n) : "memory")

// ---------------- pre-pass: fp32 -> plain fp16 -----------------------------
__global__ void conv4(const float4* __restrict__ src, uint2* __restrict__ d, int n4) {
  int i = blockIdx.x * blockDim.x + threadIdx.x;
  if (i >= n4) return;
  float4 v = src[i];
  d[i] = make_uint2(pack2h(v.x, v.y), pack2h(v.z, v.w));
}

// ---------------------------------------------------------------------------
// Plain fp16 GEMM: 1 mma per k16 chunk. CTA 128x128, kstep 32, 8 warps
// (2m x 4n), warp tile 64x32, 2 CTA/SM.
// SMEM (u16): A[2][128][40] @0 | B[2][32][136] @10240  -> 18944 u16 = 37,888 B
// MODE 0: epilogue gate(+scale) -> Q/K plain, V^T plain. MODE 1: +bias -> C.
// ---------------------------------------------------------------------------
#define GEMM_SMEM 37888

template <int LDB, int MODE>
__global__ __launch_bounds__(256) void gemm_mma(
    const unsigned short* __restrict__ Af,
    const unsigned short* __restrict__ Bg,
    const float* __restrict__ aux, float* __restrict__ C)
{
  extern __shared__ __align__(16) unsigned short smem_u16[];
  const int tid = threadIdx.x, lane = tid & 31, warp = tid >> 5;
  const int g = lane >> 2, tg = lane & 3;
  const int wm = (warp >> 2) * 64, wn = (warp & 3) * 32;
  const int bx = blockIdx.x, by = blockIdx.y;

  float acc[4][4][4] = {};

  const unsigned sbase = (unsigned)__cvta_generic_to_shared(smem_u16);
  const unsigned aoff = ((wm + (lane & 15)) * 40 + (lane >> 4) * 8) * 2;
  const unsigned boff = ((lane & 15) * 136 + wn + (lane >> 4) * 8) * 2;

  auto load_stage = [&](int k0, int st) {
    unsigned short* dA = smem_u16 + st * 5120;
    unsigned short* dB = smem_u16 + 10240 + st * 4352;
#pragma unroll
    for (int t = 0; t < 2; t++) {
      int c = tid + t * 256;
      int ar = c >> 2, ak = (c & 3) * 8;      // A: 128 rows x 4 chunks
      cp16(dA + ar * 40 + ak, Af + (size_t)(by * 128 + ar) * D_ + k0 + ak);
      int br = c >> 4, bn = (c & 15) * 8;     // B: 32 rows x 16 chunks
      cp16(dB + br * 136 + bn, Bg + (size_t)(k0 + br) * LDB + bx * 128 + bn);
    }
    CP_COMMIT();
  };

  load_stage(0, 0);
  for (int it = 0; it < 24; it++) {
    if (it + 1 < 24) {
      load_stage((it + 1) * 32, (it + 1) & 1);
      CP_WAIT(1);
    } else {
      CP_WAIT(0);
    }
    __syncthreads();
    const int st = it & 1;
    const unsigned sA = sbase + st * 10240;
    const unsigned sB = sbase + 20480 + st * 8704;
#pragma unroll
    for (int kk = 0; kk < 2; kk++) {
      unsigned af[4][4], bf[2][4];
#pragma unroll
      for (int i = 0; i < 4; i++)
        ldsm4(af[i], sA + aoff + i * 1280 + kk * 32);
#pragma unroll
      for (int jj = 0; jj < 2; jj++)
        ldsm4t(bf[jj], sB + boff + kk * 4352 + jj * 32);
#pragma unroll
      for (int i = 0; i < 4; i++)
#pragma unroll
        for (int jj = 0; jj < 2; jj++) {
          mmah(acc[i][2 * jj],     af[i], bf[jj][0], bf[jj][1]);
          mmah(acc[i][2 * jj + 1], af[i], bf[jj][2], bf[jj][3]);
        }
    }
    __syncthreads();
  }

  if constexpr (MODE == 0) {
    const int which = bx / 6;   // 0=Q 1=K 2=V
#pragma unroll
    for (int i = 0; i < 4; i++) {
#pragma unroll
      for (int half = 0; half < 2; half++) {
        const int m = by * 128 + wm + i * 16 + g + half * 8;
        const float gate = aux[m];
        const int b = m >> 10, tok = m & 1023;
#pragma unroll
        for (int j = 0; j < 4; j++) {
          const int col = bx * 128 + wn + j * 8 + 2 * tg;
          const int dd = col - which * D_;
          const int h = dd >> 6, hd = dd & 63;
          const int bh = b * H_ + h;
          float v0 = acc[i][j][half * 2 + 0] * gate;
          float v1 = acc[i][j][half * 2 + 1] * gate;
          if (which == 0) {
            v0 *= SCALE_; v1 *= SCALE_;
            const size_t idx = ((size_t)bh * N_ + tok) * HD_ + hd;
            *reinterpret_cast<unsigned*>(&g_Qf[idx]) = pack2h(v0, v1);
          } else if (which == 1) {
            const size_t idx = ((size_t)bh * N_ + tok) * HD_ + hd;
            *reinterpret_cast<unsigned*>(&g_Kf[idx]) = pack2h(v0, v1);
          } else {
            const unsigned Hv = pack2h(v0, v1);
            const size_t r0 = ((size_t)bh * HD_ + hd) * N_ + tok;
            g_Vt[r0] = (unsigned short)Hv;
            g_Vt[r0 + N_] = (unsigned short)(Hv >> 16);
          }
        }
      }
    }
  } else {
#pragma unroll
    for (int i = 0; i < 4; i++)
#pragma unroll
      for (int half = 0; half < 2; half++) {
        const int m = by * 128 + wm + i * 16 + g + half * 8;
#pragma unroll
        for (int j = 0; j < 4; j++) {
          const int col = bx * 128 + wn + j * 8 + 2 * tg;
          float2 o;
          o.x = acc[i][j][half * 2 + 0] + aux[col];
          o.y = acc[i][j][half * 2 + 1] + aux[col + 1];
          *reinterpret_cast<float2*>(&C[(size_t)m * D_ + col]) = o;
        }
      }
  }
}

// ---------------------------------------------------------------------------
// Flash attention, plain fp16 (1 mma/chunk): 128 queries/CTA, online softmax,
// S/P in registers. K buffer (128x72 u16) + V^T buffer (64x136 u16),
// prefetch next tile after each consumer phase.
// SMEM total 35,840 B.
// ---------------------------------------------------------------------------
#define FA_VOFF 18432      // byte offset of V buffer
#define FA_SMEM 35840

__global__ __launch_bounds__(256, 1) void attn_flash()
{
  extern __shared__ __align__(16) unsigned short KV[];
  const unsigned kvb = (unsigned)__cvta_generic_to_shared(KV);

  const int tid = threadIdx.x, lane = tid & 31, warp = tid >> 5;
  const int g = lane >> 2, tg = lane & 3;
  const int bh = blockIdx.y;
  const int q0 = blockIdx.x * 128;
  const size_t kbase = (size_t)bh * N_ * HD_;
  const size_t vbase = (size_t)bh * HD_ * N_;
  const size_t qrow = kbase + (size_t)(q0 + warp * 16 + g) * HD_;

  auto load_k = [&](int kt) {
    unsigned short* dst = KV;
    const unsigned short* sk = g_Kf + kbase + (size_t)kt * 128 * HD_;
    // K tile: 128 rows x 64 halves = 1024 chunks of 16B  (t < 4 !)
#pragma unroll
    for (int t = 0; t < 4; t++) {
      int c = tid + t * 256;
      int row = c >> 3, ko = (c & 7) * 8;
      cp16(dst + row * 72 + ko, sk + row * HD_ + ko);
    }
    CP_COMMIT();
  };
  auto load_v = [&](int vt) {
    unsigned short* dst = KV + 9216;   // u16 offset of V buffer
    const unsigned short* sv = g_Vt + vbase + vt * 128;
    // V tile: 64 rows x 128 halves = 1024 chunks of 16B
#pragma unroll
    for (int t = 0; t < 4; t++) {
      int c = tid + t * 256;
      int row = c >> 4, no = (c & 15) * 8;
      cp16(dst + row * 136 + no, sv + (size_t)row * N_ + no);
    }
    CP_COMMIT();
  };

  load_k(0);
  load_v(0);

  // resident Q fragments: plain fp16, 4 k16 chunks
  unsigned qf[4][4];
#pragma unroll
  for (int c = 0; c < 4; c++) {
    const size_t r0 = qrow + c * 16 + 2 * tg;
    const size_t r8 = r0 + 8 * HD_;
    qf[c][0] = *reinterpret_cast<const unsigned*>(&g_Qf[r0]);
    qf[c][1] = *reinterpret_cast<const unsigned*>(&g_Qf[r8]);
    qf[c][2] = *reinterpret_cast<const unsigned*>(&g_Qf[r0 + 8]);
    qf[c][3] = *reinterpret_cast<const unsigned*>(&g_Qf[r8 + 8]);
  }

  float oacc[8][4] = {};
  float m0 = -1e30f, m1 = -1e30f, l0 = 0.f, l1 = 0.f;

  const unsigned kfb = ((lane & 15) * 72 + (lane >> 4) * 8) * 2;
  const unsigned vfb = ((lane & 7) * 136 + (lane >> 3) * 8) * 2;

#pragma unroll 1
  for (int kt = 0; kt < 8; kt++) {
    // ---- S = Q K^T ----
    CP_WAIT(1);
    __syncthreads();
    float sacc[16][4] = {};
#pragma unroll
    for (int kg = 0; kg < 8; kg++) {
      const unsigned kb = kvb + kg * 2304 + kfb;
      unsigned kh[4][4];
#pragma unroll
      for (int c = 0; c < 4; c++)
        ldsm4(kh[c], kb + c * 32);
      float* s0 = sacc[2 * kg];
      float* s1 = sacc[2 * kg + 1];
#pragma unroll
      for (int c = 0; c < 4; c++) {
        mmah(s0, qf[c], kh[c][0], kh[c][2]);
        mmah(s1, qf[c], kh[c][1], kh[c][3]);
      }
    }
    __syncthreads();
    if (kt < 7) load_k(kt + 1);

    // ---- online softmax; emit plain-fp16 P fragment words ----
    float mx0 = -1e30f, mx1 = -1e30f;
#pragma unroll
    for (int t = 0; t < 16; t++) {
      mx0 = fmaxf(mx0, fmaxf(sacc[t][0], sacc[t][1]));
      mx1 = fmaxf(mx1, fmaxf(sacc[t][2], sacc[t][3]));
    }
    mx0 = fmaxf(mx0, __shfl_xor_sync(0xffffffffu, mx0, 1));
    mx0 = fmaxf(mx0, __shfl_xor_sync(0xffffffffu, mx0, 2));
    mx1 = fmaxf(mx1, __shfl_xor_sync(0xffffffffu, mx1, 1));
    mx1 = fmaxf(mx1, __shfl_xor_sync(0xffffffffu, mx1, 2));
    const float m0n = fmaxf(m0, mx0), m1n = fmaxf(m1, mx1);
    const float c0 = __expf(m0 - m0n), c1 = __expf(m1 - m1n);
    m0 = m0n; m1 = m1n;
    float ts0 = 0.f, ts1 = 0.f;
#pragma unroll
    for (int t = 0; t < 16; t++) {
      float p0 = __expf(sacc[t][0] - m0n), p1 = __expf(sacc[t][1] - m0n);
      float p2 = __expf(sacc[t][2] - m1n), p3 = __expf(sacc[t][3] - m1n);
      ts0 += p0 + p1; ts1 += p2 + p3;
      sacc[t][0] = __uint_as_float(pack2h(p0, p1));   // rows g pair
      sacc[t][2] = __uint_as_float(pack2h(p2, p3));   // rows g+8 pair
    }
    ts0 += __shfl_xor_sync(0xffffffffu, ts0, 1);
    ts0 += __shfl_xor_sync(0xffffffffu, ts0, 2);
    ts1 += __shfl_xor_sync(0xffffffffu, ts1, 1);
    ts1 += __shfl_xor_sync(0xffffffffu, ts1, 2);
    l0 = l0 * c0 + ts0;
    l1 = l1 * c1 + ts1;
#pragma unroll
    for (int vn = 0; vn < 8; vn++) {
      oacc[vn][0] *= c0; oacc[vn][1] *= c0;
      oacc[vn][2] *= c1; oacc[vn][3] *= c1;
    }

    // ---- O += P V ----
    CP_WAIT(1);
    if (kt == 7) CP_WAIT(0);
    __syncthreads();
#pragma unroll
    for (int tt = 0; tt < 4; tt++) {
      unsigned pf[2][4];
#pragma unroll
      for (int cc = 0; cc < 2; cc++) {
        const int t0 = (2 * tt + cc) * 2;
        pf[cc][0] = __float_as_uint(sacc[t0][0]);
        pf[cc][1] = __float_as_uint(sacc[t0][2]);
        pf[cc][2] = __float_as_uint(sacc[t0 + 1][0]);
        pf[cc][3] = __float_as_uint(sacc[t0 + 1][2]);
      }
#pragma unroll
      for (int vp = 0; vp < 4; vp++) {
        const int vn0 = 2 * vp, vn1 = 2 * vp + 1;
        const unsigned vb0 = kvb + FA_VOFF + vn0 * 2176 + vfb + tt * 64;
        const unsigned vb1 = kvb + FA_VOFF + vn1 * 2176 + vfb + tt * 64;
        unsigned vh0[4], vh1[4];
        ldsm4(vh0, vb0);
        ldsm4(vh1, vb1);
        float* o0 = oacc[vn0];
        float* o1 = oacc[vn1];
        mmah(o0, pf[0], vh0[0], vh0[1]);
        mmah(o1, pf[0], vh1[0], vh1[1]);
        mmah(o0, pf[1], vh0[2], vh0[3]);
        mmah(o1, pf[1], vh1[2], vh1[3]);
      }
    }
    __syncthreads();
    if (kt < 7) load_v(kt + 1);
  }

  // ---- finalize: normalize, write plain fp16 O (A-side of GEMM2) ----
  const float inv0 = 1.f / l0, inv1 = 1.f / l1;
  const int b = bh / H_, h = bh - (bh / H_) * H_;
  const int tok = q0 + warp * 16 + g;
  const size_t base0 = (size_t)(b * N_ + tok) * D_ + h * HD_ + 2 * tg;
  const size_t base8 = base0 + (size_t)8 * D_;
#pragma unroll
  for (int vn = 0; vn < 8; vn++) {
    *reinterpret_cast<unsigned*>(&g_Af[base0 + vn * 8]) =
        pack2h(oacc[vn][0] * inv0, oacc[vn][1] * inv0);
    *reinterpret_cast<unsigned*>(&g_Af[base8 + vn * 8]) =
        pack2h(oacc[vn][2] * inv1, oacc[vn][3] * inv1);
  }
}

// ---------------------------------------------------------------------------
extern "C" void kernel_launch(void* const* d_in, const int* in_sizes, int n_in,
                              void* d_out, int out_size)
{
  const float* x      = (const float*)d_in[0];
  const float* weight = (const float*)d_in[1];
  const float* W_qkv  = (const float*)d_in[2];
  const float* W_msa  = (const float*)d_in[3];
  const float* b_msa  = (const float*)d_in[4];
  float* out = (float*)d_out;

  unsigned short *xf, *wq, *wm, *af;
  cudaGetSymbolAddress((void**)&xf, g_Xf);
  cudaGetSymbolAddress((void**)&wq, g_Wq);
  cudaGetSymbolAddress((void**)&wm, g_Wm);
  cudaGetSymbolAddress((void**)&af, g_Af);

  cudaFuncSetAttribute(gemm_mma<D3_, 0>,
                       cudaFuncAttributeMaxDynamicSharedMemorySize, GEMM_SMEM);
  cudaFuncSetAttribute(gemm_mma<D_, 1>,
                       cudaFuncAttributeMaxDynamicSharedMemorySize, GEMM_SMEM);
  cudaFuncSetAttribute(attn_flash,
                       cudaFuncAttributeMaxDynamicSharedMemorySize, FA_SMEM);

  // 0) pre-pass: everything -> plain fp16
  conv4<<<ROWS * D_ / 4 / 256, 256>>>((const float4*)x, (uint2*)xf, ROWS * D_ / 4);
  conv4<<<D_ * D3_ / 4 / 256, 256>>>((const float4*)W_qkv, (uint2*)wq, D_ * D3_ / 4);
  conv4<<<D_ * D_ / 4 / 256, 256>>>((const float4*)W_msa, (uint2*)wm, D_ * D_ / 4);
  // 1) QKV projection + gate + head-major scatter
  gemm_mma<D3_, 0><<<dim3(D3_ / 128, ROWS / 128), 256, GEMM_SMEM>>>(
      xf, wq, weight, nullptr);
  // 2) flash attention
  attn_flash<<<dim3(N_ / 128, NBH), 256, FA_SMEM>>>();
  // 3) output projection + bias
  gemm_mma<D_, 1><<<dim3(D_ / 128, ROWS / 128), 256, GEMM_SMEM>>>(
      af, wm, b_msa, out);
}